// round 8
// baseline (speedup 1.0000x reference)
#include <cuda_runtime.h>
#include <math.h>

#define NT 512
typedef unsigned long long ull;

// ---- packed f32x2 helpers (sm_103a) ----
__device__ __forceinline__ ull pk2(float lo, float hi) {
    ull r; asm("mov.b64 %0, {%1,%2};" : "=l"(r) : "f"(lo), "f"(hi)); return r;
}
__device__ __forceinline__ float2 upk2(ull v) {
    float2 r; asm("mov.b64 {%0,%1}, %2;" : "=f"(r.x), "=f"(r.y) : "l"(v)); return r;
}
__device__ __forceinline__ ull ffma2(ull a, ull b, ull c) {
    ull d; asm("fma.rn.f32x2 %0, %1, %2, %3;" : "=l"(d) : "l"(a), "l"(b), "l"(c)); return d;
}
__device__ __forceinline__ void loadx(const float* p, ull* xp) {
    const float4* p4 = (const float4*)p;
#pragma unroll
    for (int i = 0; i < 4; i++) {
        float4 v = p4[i];
        xp[2*i]   = pk2(v.x, v.y);
        xp[2*i+1] = pk2(v.z, v.w);
    }
}
// dot16 with packed x and a GLOBAL float4 weight row (ldg)
__device__ __forceinline__ float dot16g(const ull* xp, const float4* __restrict__ w4) {
    float4 w0 = __ldg(w4), w1 = __ldg(w4+1), w2 = __ldg(w4+2), w3 = __ldg(w4+3);
    ull a0 = 0ull, a1 = 0ull;
    a0 = ffma2(xp[0], pk2(w0.x, w0.y), a0); a1 = ffma2(xp[1], pk2(w0.z, w0.w), a1);
    a0 = ffma2(xp[2], pk2(w1.x, w1.y), a0); a1 = ffma2(xp[3], pk2(w1.z, w1.w), a1);
    a0 = ffma2(xp[4], pk2(w2.x, w2.y), a0); a1 = ffma2(xp[5], pk2(w2.z, w2.w), a1);
    a0 = ffma2(xp[6], pk2(w3.x, w3.y), a0); a1 = ffma2(xp[7], pk2(w3.z, w3.w), a1);
    float2 s0 = upk2(a0), s1 = upk2(a1);
    return (s0.x + s1.x) + (s0.y + s1.y);
}

__global__ __launch_bounds__(NT, 1) void fused_kernel(
    const float* __restrict__ t,
    const float* __restrict__ gat_W, const float* __restrict__ a_src, const float* __restrict__ a_dst,
    const float* __restrict__ te_W, const float* __restrict__ te_b, const float* __restrict__ pe,
    const float* __restrict__ qkv_W, const float* __restrict__ qkv_b,
    const float* __restrict__ out_W, const float* __restrict__ out_b,
    const float* __restrict__ ln1_g, const float* __restrict__ ln1_b,
    const float* __restrict__ ff1_W, const float* __restrict__ ff1_b,
    const float* __restrict__ ff2_W, const float* __restrict__ ff2_b,
    const float* __restrict__ ln2_g, const float* __restrict__ ln2_b,
    const float* __restrict__ an_W, const float* __restrict__ an_b,
    const float* __restrict__ pr_W, const float* __restrict__ pr_b,
    float* __restrict__ out)
{
    const int tid  = threadIdx.x;
    const int warp = tid >> 5;
    const int lane = tid & 31;
    const int g    = warp & 1;
    const int tk   = g * 32 + lane;
    const int pp   = warp >> 1;
    const bool tok_ok = tk < 48;

    // ---- decoder weight prefetch (registers; hidden behind encoder) ----
    const int row = blockIdx.x * 16 + warp;   // 0..159
    const float4* wp = (row < 32) ? (const float4*)(an_W + row * 768)
                                  : (const float4*)(pr_W + (row - 32) * 768);
    float bias_reg = (row < 32) ? an_b[row] : pr_b[row - 32];
    float4 wreg[6];
#pragma unroll
    for (int i = 0; i < 6; i++) wreg[i] = __ldg(wp + i * 32 + lane);

    // activations only in smem
    __shared__ float A_h[48 * 20];
    __shared__ float A_xe[48 * 20];
    __shared__ float A_qkv[48 * 52];
    __shared__ float A_hid[48 * 68];
    __shared__ float A_e[96];

    // ---- P1: h row + e_src/e_dst (1 thread per token) ----
    if (tid < 48) {
        float x0 = __ldg(t + tid*3), x1 = __ldg(t + tid*3 + 1), x2 = __ldg(t + tid*3 + 2);
        float hrow[16];
        float es = 0.f, ed = 0.f;
#pragma unroll
        for (int f = 0; f < 16; f++) {
            float hv = x0*__ldg(gat_W+f) + x1*__ldg(gat_W+16+f) + x2*__ldg(gat_W+32+f);
            hrow[f] = hv;
            es += hv * __ldg(a_src+f);
            ed += hv * __ldg(a_dst+f);
        }
#pragma unroll
        for (int i = 0; i < 4; i++)
            *(float4*)(A_h + tid*20 + i*4) = make_float4(hrow[4*i], hrow[4*i+1], hrow[4*i+2], hrow[4*i+3]);
        A_e[tid] = es;
        A_e[48 + tid] = ed;
    }
    __syncthreads();

    // ---- P2: alpha softmax + aggregate + ELU + time-encode + pe (1 thread per token) ----
    if (tid < 48) {
        int w = tid >> 4;
        float ed = A_e[48 + tid];
        float vals[16], mx = -1e30f;
#pragma unroll
        for (int s = 0; s < 16; s++) {
            float e = A_e[w * 16 + s] + ed;
            e = (e > 0.f) ? e : 0.2f * e;
            vals[s] = e; mx = fmaxf(mx, e);
        }
        float sum = 0.f;
#pragma unroll
        for (int s = 0; s < 16; s++) { vals[s] = __expf(vals[s] - mx); sum += vals[s]; }
        float inv = 1.f / sum;
        ull acc[8] = {0,0,0,0,0,0,0,0};
#pragma unroll
        for (int ss = 0; ss < 16; ss++) {
            const float4* hr = (const float4*)(A_h + (w * 16 + ss) * 20);
            ull av = pk2(vals[ss] * inv, vals[ss] * inv);
#pragma unroll
            for (int i = 0; i < 4; i++) {
                float4 hv = hr[i];
                acc[2*i]   = ffma2(av, pk2(hv.x, hv.y), acc[2*i]);
                acc[2*i+1] = ffma2(av, pk2(hv.z, hv.w), acc[2*i+1]);
            }
        }
        ull xp[8];
#pragma unroll
        for (int i = 0; i < 8; i++) {
            float2 v = upk2(acc[i]);
            float a = (v.x > 0.f) ? v.x : (__expf(v.x) - 1.f);
            float b = (v.y > 0.f) ? v.y : (__expf(v.y) - 1.f);
            xp[i] = pk2(a, b);
        }
        float y[16];
#pragma unroll
        for (int d = 0; d < 16; d++)
            y[d] = __ldg(te_b + d) + __ldg(pe + w * 16 + d) +
                   dot16g(xp, (const float4*)(te_W + d * 16));
#pragma unroll
        for (int i = 0; i < 4; i++)
            *(float4*)(A_xe + tid*20 + i*4) = make_float4(y[4*i], y[4*i+1], y[4*i+2], y[4*i+3]);
    }
    __syncthreads();

    const float inv_sqrt_hd = 0.35355339059327373f;

    for (int l = 0; l < 2; l++) {
        // ---- qkv (16 warps; 6 outputs per active lane) ----
        if (tok_ok) {
            ull xp[8]; loadx(A_xe + tk * 20, xp);
#pragma unroll
            for (int i6 = 0; i6 < 6; i6++) {
                int j = pp + i6 * 8;
                A_qkv[tk * 52 + j] = __ldg(qkv_b + l * 48 + j) +
                    dot16g(xp, (const float4*)(qkv_W + l * 768 + j * 16));
            }
        }
        __syncthreads();

        // ---- attention + out-proj + residual + LN1 (2 threads/token, fused) ----
        if (tid < 96) {
            int tk2 = tid >> 1, h2 = tid & 1;
            int b = tk2 & 15;
            const float4* qr = (const float4*)(A_qkv + tk2 * 52 + h2 * 8);
            float4 q0 = qr[0], q1 = qr[1];
            float sc[3], mx = -1e30f;
#pragma unroll
            for (int ks = 0; ks < 3; ks++) {
                const float4* kr = (const float4*)(A_qkv + (ks * 16 + b) * 52 + 16 + h2 * 8);
                float4 k0 = kr[0], k1 = kr[1];
                float s = q0.x*k0.x + q0.y*k0.y + q0.z*k0.z + q0.w*k0.w
                        + q1.x*k1.x + q1.y*k1.y + q1.z*k1.z + q1.w*k1.w;
                s *= inv_sqrt_hd;
                sc[ks] = s; mx = fmaxf(mx, s);
            }
            float sum = 0.f;
#pragma unroll
            for (int ks = 0; ks < 3; ks++) { sc[ks] = __expf(sc[ks] - mx); sum += sc[ks]; }
            float inv = 1.f / sum;
            float ctx[8] = {0,0,0,0,0,0,0,0};
#pragma unroll
            for (int ks = 0; ks < 3; ks++) {
                const float4* vr = (const float4*)(A_qkv + (ks * 16 + b) * 52 + 32 + h2 * 8);
                float4 v0 = vr[0], v1 = vr[1];
                float w = sc[ks];
                ctx[0] += w*v0.x; ctx[1] += w*v0.y; ctx[2] += w*v0.z; ctx[3] += w*v0.w;
                ctx[4] += w*v1.x; ctx[5] += w*v1.y; ctx[6] += w*v1.z; ctx[7] += w*v1.w;
            }
#pragma unroll
            for (int e = 0; e < 8; e++) ctx[e] *= inv;
            float full[16];
#pragma unroll
            for (int e = 0; e < 8; e++) {
                float o = __shfl_xor_sync(0xffffffffu, ctx[e], 1);
                if (h2 == 0) { full[e] = ctx[e]; full[8+e] = o; }
                else         { full[e] = o;      full[8+e] = ctx[e]; }
            }
            ull xp[8];
#pragma unroll
            for (int i = 0; i < 8; i++) xp[i] = pk2(full[2*i], full[2*i+1]);
            float4 r0 = *(const float4*)(A_xe + tk2 * 20 + h2 * 8);
            float4 r1 = *(const float4*)(A_xe + tk2 * 20 + h2 * 8 + 4);
            float resid[8] = { r0.x, r0.y, r0.z, r0.w, r1.x, r1.y, r1.z, r1.w };
            float y[8];
#pragma unroll
            for (int k = 0; k < 8; k++) {
                int d = h2 * 8 + k;
                y[k] = __ldg(out_b + l * 16 + d) + resid[k] +
                       dot16g(xp, (const float4*)(out_W + l * 256 + d * 16));
            }
            float ls = 0.f, lq = 0.f;
#pragma unroll
            for (int k = 0; k < 8; k++) { ls += y[k]; lq += y[k] * y[k]; }
            ls += __shfl_xor_sync(0xffffffffu, ls, 1);
            lq += __shfl_xor_sync(0xffffffffu, lq, 1);
            float m = ls * 0.0625f;
            float rin = rsqrtf(lq * 0.0625f - m * m + 1e-5f);
#pragma unroll
            for (int k = 0; k < 8; k++) {
                int d = h2 * 8 + k;
                y[k] = (y[k] - m) * rin * __ldg(ln1_g + l * 16 + d) + __ldg(ln1_b + l * 16 + d);
            }
            *(float4*)(A_xe + tk2 * 20 + h2 * 8)     = make_float4(y[0], y[1], y[2], y[3]);
            *(float4*)(A_xe + tk2 * 20 + h2 * 8 + 4) = make_float4(y[4], y[5], y[6], y[7]);
        }
        __syncthreads();

        // ---- ff1 (relu), 8 contiguous outputs per active lane ----
        if (tok_ok) {
            ull xp[8]; loadx(A_xe + tk * 20, xp);
            float y[8];
#pragma unroll
            for (int k = 0; k < 8; k++) {
                int f = pp * 8 + k;
                y[k] = fmaxf(__ldg(ff1_b + l * 64 + f) +
                             dot16g(xp, (const float4*)(ff1_W + l * 1024 + f * 16)), 0.f);
            }
            *(float4*)(A_hid + tk * 68 + pp * 8)     = make_float4(y[0], y[1], y[2], y[3]);
            *(float4*)(A_hid + tk * 68 + pp * 8 + 4) = make_float4(y[4], y[5], y[6], y[7]);
        }
        __syncthreads();

        // ---- ff2 + residual + LN2 (4 threads/token) ----
        if (tid < 192) {
            int tk2 = tid >> 2, q = tid & 3;
            const float4* hr = (const float4*)(A_hid + tk2 * 68);
            const float4* w40 = (const float4*)(ff2_W + l * 1024 + (q * 4 + 0) * 64);
            const float4* w41 = (const float4*)(ff2_W + l * 1024 + (q * 4 + 1) * 64);
            const float4* w42 = (const float4*)(ff2_W + l * 1024 + (q * 4 + 2) * 64);
            const float4* w43 = (const float4*)(ff2_W + l * 1024 + (q * 4 + 3) * 64);
            ull a0[4] = {0,0,0,0}, a1[4] = {0,0,0,0};
#pragma unroll
            for (int i = 0; i < 16; i++) {
                float4 h4 = hr[i];
                ull h0 = pk2(h4.x, h4.y), h1 = pk2(h4.z, h4.w);
                float4 w0 = __ldg(w40+i), w1 = __ldg(w41+i), w2 = __ldg(w42+i), w3 = __ldg(w43+i);
                a0[0] = ffma2(h0, pk2(w0.x, w0.y), a0[0]); a1[0] = ffma2(h1, pk2(w0.z, w0.w), a1[0]);
                a0[1] = ffma2(h0, pk2(w1.x, w1.y), a0[1]); a1[1] = ffma2(h1, pk2(w1.z, w1.w), a1[1]);
                a0[2] = ffma2(h0, pk2(w2.x, w2.y), a0[2]); a1[2] = ffma2(h1, pk2(w2.z, w2.w), a1[2]);
                a0[3] = ffma2(h0, pk2(w3.x, w3.y), a0[3]); a1[3] = ffma2(h1, pk2(w3.z, w3.w), a1[3]);
            }
            float y[4], ls = 0.f, lq = 0.f;
#pragma unroll
            for (int k = 0; k < 4; k++) {
                int d = q * 4 + k;
                float2 s0 = upk2(a0[k]), s1 = upk2(a1[k]);
                y[k] = (s0.x + s1.x) + (s0.y + s1.y) + __ldg(ff2_b + l * 16 + d) + A_xe[tk2 * 20 + d];
                ls += y[k]; lq += y[k] * y[k];
            }
            ls += __shfl_xor_sync(0xffffffffu, ls, 1);
            lq += __shfl_xor_sync(0xffffffffu, lq, 1);
            ls += __shfl_xor_sync(0xffffffffu, ls, 2);
            lq += __shfl_xor_sync(0xffffffffu, lq, 2);
            float m = ls * 0.0625f;
            float rin = rsqrtf(lq * 0.0625f - m * m + 1e-5f);
#pragma unroll
            for (int k = 0; k < 4; k++) {
                int d = q * 4 + k;
                y[k] = (y[k] - m) * rin * __ldg(ln2_g + l * 16 + d) + __ldg(ln2_b + l * 16 + d);
            }
            *(float4*)(A_xe + tk2 * 20 + q * 4) = make_float4(y[0], y[1], y[2], y[3]);
        }
        __syncthreads();
    }

    // ---- decoder: warp = output row, latent read from smem ----
    {
        ull a0 = 0ull, a1 = 0ull;
#pragma unroll
        for (int i = 0; i < 6; i++) {
            int j = i * 128 + 4 * lane;        // latent index (host-major)
            int n = j / 48, rem = j - n * 48;
            int ww = rem >> 4, d = rem & 15;
            float4 x = *(const float4*)(A_xe + (ww * 16 + n) * 20 + d);
            a0 = ffma2(pk2(x.x, x.y), pk2(wreg[i].x, wreg[i].y), a0);
            a1 = ffma2(pk2(x.z, x.w), pk2(wreg[i].z, wreg[i].w), a1);
        }
        float2 s0 = upk2(a0), s1 = upk2(a1);
        float s = (s0.x + s1.x) + (s0.y + s1.y);
#pragma unroll
        for (int o = 16; o; o >>= 1) s += __shfl_xor_sync(0xffffffffu, s, o);
        if (lane == 0) {
            s += bias_reg;
            if (row >= 32) s = 1.f / (1.f + __expf(-s));
            out[row] = s;
        }
    }
}

extern "C" void kernel_launch(void* const* d_in, const int* in_sizes, int n_in,
                              void* d_out, int out_size) {
    fused_kernel<<<10, NT>>>(
        (const float*)d_in[0],
        (const float*)d_in[2], (const float*)d_in[3], (const float*)d_in[4],
        (const float*)d_in[5], (const float*)d_in[6], (const float*)d_in[7],
        (const float*)d_in[8], (const float*)d_in[9],
        (const float*)d_in[10], (const float*)d_in[11],
        (const float*)d_in[12], (const float*)d_in[13],
        (const float*)d_in[14], (const float*)d_in[15],
        (const float*)d_in[16], (const float*)d_in[17],
        (const float*)d_in[18], (const float*)d_in[19],
        (const float*)d_in[20], (const float*)d_in[21],
        (const float*)d_in[22], (const float*)d_in[23],
        (float*)d_out);
}

// round 9
// speedup vs baseline: 1.2133x; 1.2133x over previous
#include <cuda_runtime.h>
#include <math.h>

#define NT 512
typedef unsigned long long ull;

// ---- packed f32x2 helpers (sm_103a) ----
__device__ __forceinline__ ull pk2(float lo, float hi) {
    ull r; asm("mov.b64 %0, {%1,%2};" : "=l"(r) : "f"(lo), "f"(hi)); return r;
}
__device__ __forceinline__ float2 upk2(ull v) {
    float2 r; asm("mov.b64 {%0,%1}, %2;" : "=f"(r.x), "=f"(r.y) : "l"(v)); return r;
}
__device__ __forceinline__ ull ffma2(ull a, ull b, ull c) {
    ull d; asm("fma.rn.f32x2 %0, %1, %2, %3;" : "=l"(d) : "l"(a), "l"(b), "l"(c)); return d;
}
__device__ __forceinline__ void loadx(const float* p, ull* xp) {
    const float4* p4 = (const float4*)p;
#pragma unroll
    for (int i = 0; i < 4; i++) {
        float4 v = p4[i];
        xp[2*i]   = pk2(v.x, v.y);
        xp[2*i+1] = pk2(v.z, v.w);
    }
}
// dot16: packed x, SMEM float4 weight row (warp-uniform -> broadcast)
__device__ __forceinline__ float dot16p(const ull* xp, const float4* w4) {
    ull a0 = 0ull, a1 = 0ull;
#pragma unroll
    for (int i = 0; i < 4; i++) {
        float4 w = w4[i];
        a0 = ffma2(xp[2*i],   pk2(w.x, w.y), a0);
        a1 = ffma2(xp[2*i+1], pk2(w.z, w.w), a1);
    }
    float2 s0 = upk2(a0), s1 = upk2(a1);
    return (s0.x + s1.x) + (s0.y + s1.y);
}
// dot16: packed x, GLOBAL float4 weight row (used only in overlapped prologue)
__device__ __forceinline__ float dot16g(const ull* xp, const float4* __restrict__ w4) {
    float4 w0 = __ldg(w4), w1 = __ldg(w4+1), w2 = __ldg(w4+2), w3 = __ldg(w4+3);
    ull a0 = 0ull, a1 = 0ull;
    a0 = ffma2(xp[0], pk2(w0.x, w0.y), a0); a1 = ffma2(xp[1], pk2(w0.z, w0.w), a1);
    a0 = ffma2(xp[2], pk2(w1.x, w1.y), a0); a1 = ffma2(xp[3], pk2(w1.z, w1.w), a1);
    a0 = ffma2(xp[4], pk2(w2.x, w2.y), a0); a1 = ffma2(xp[5], pk2(w2.z, w2.w), a1);
    a0 = ffma2(xp[6], pk2(w3.x, w3.y), a0); a1 = ffma2(xp[7], pk2(w3.z, w3.w), a1);
    float2 s0 = upk2(a0), s1 = upk2(a1);
    return (s0.x + s1.x) + (s0.y + s1.y);
}

__global__ __launch_bounds__(NT, 1) void fused_kernel(
    const float* __restrict__ t,
    const float* __restrict__ gat_W, const float* __restrict__ a_src, const float* __restrict__ a_dst,
    const float* __restrict__ te_W, const float* __restrict__ te_b, const float* __restrict__ pe,
    const float* __restrict__ qkv_W, const float* __restrict__ qkv_b,
    const float* __restrict__ out_W, const float* __restrict__ out_b,
    const float* __restrict__ ln1_g, const float* __restrict__ ln1_b,
    const float* __restrict__ ff1_W, const float* __restrict__ ff1_b,
    const float* __restrict__ ff2_W, const float* __restrict__ ff2_b,
    const float* __restrict__ ln2_g, const float* __restrict__ ln2_b,
    const float* __restrict__ an_W, const float* __restrict__ an_b,
    const float* __restrict__ pr_W, const float* __restrict__ pr_b,
    float* __restrict__ out)
{
    const int tid  = threadIdx.x;
    const int warp = tid >> 5;
    const int lane = tid & 31;
    const int g    = warp & 1;
    const int tk   = g * 32 + lane;
    const int pp   = warp >> 1;
    const bool tok_ok = tk < 48;

    // ---- decoder weight prefetch (registers; hidden behind encoder) ----
    const int row = blockIdx.x * 16 + warp;   // 0..159
    const float4* wp = (row < 32) ? (const float4*)(an_W + row * 768)
                                  : (const float4*)(pr_W + (row - 32) * 768);
    float bias_reg = (row < 32) ? an_b[row] : pr_b[row - 32];
    float4 wreg[6];
#pragma unroll
    for (int i = 0; i < 6; i++) wreg[i] = __ldg(wp + i * 32 + lane);

    extern __shared__ float sm[];
    // weights, unpadded (all phase reads are warp-uniform broadcasts)
    float* s_qkvW = sm;            // 1536
    float* s_qkvb = sm + 1536;     // 96
    float* s_outW = sm + 1632;     // 512
    float* s_outb = sm + 2144;     // 32
    float* s_ln1g = sm + 2176;     // 32
    float* s_ln1b = sm + 2208;     // 32
    float* s_ff1W = sm + 2240;     // 2048
    float* s_ff1b = sm + 4288;     // 128
    float* s_ff2W = sm + 4416;     // 2048
    float* s_ff2b = sm + 6464;     // 32
    float* s_ln2g = sm + 6496;     // 32
    float* s_ln2b = sm + 6528;     // 32
    // activations, padded strides (per-lane access)
    float* A_h    = sm + 6560;     // 48*20
    float* A_xe   = sm + 7520;     // 48*20
    float* A_qkv  = sm + 8480;     // 48*52
    float* A_hid  = sm + 10976;    // 48*68
    float* A_e    = sm + 14240;    // 96

    if (warp < 2) {
        // ======== overlapped prologue: GAT P1 + P2 (weights direct from L2) ========
        if (tid < 48) {
            float x0 = __ldg(t + tid*3), x1 = __ldg(t + tid*3 + 1), x2 = __ldg(t + tid*3 + 2);
            float hrow[16];
            float es = 0.f, ed = 0.f;
#pragma unroll
            for (int f = 0; f < 16; f++) {
                float hv = x0*__ldg(gat_W+f) + x1*__ldg(gat_W+16+f) + x2*__ldg(gat_W+32+f);
                hrow[f] = hv;
                es += hv * __ldg(a_src+f);
                ed += hv * __ldg(a_dst+f);
            }
#pragma unroll
            for (int i = 0; i < 4; i++)
                *(float4*)(A_h + tid*20 + i*4) = make_float4(hrow[4*i], hrow[4*i+1], hrow[4*i+2], hrow[4*i+3]);
            A_e[tid] = es;
            A_e[48 + tid] = ed;
        }
        __syncwarp();   // window w lives entirely in one warp -> intra-warp dep only
        if (tid < 48) {
            int w = tid >> 4;
            float ed = A_e[48 + tid];
            float vals[16], mx = -1e30f;
#pragma unroll
            for (int s = 0; s < 16; s++) {
                float e = A_e[w * 16 + s] + ed;
                e = (e > 0.f) ? e : 0.2f * e;
                vals[s] = e; mx = fmaxf(mx, e);
            }
            float sum = 0.f;
#pragma unroll
            for (int s = 0; s < 16; s++) { vals[s] = __expf(vals[s] - mx); sum += vals[s]; }
            float inv = 1.f / sum;
            ull acc[8] = {0,0,0,0,0,0,0,0};
#pragma unroll
            for (int ss = 0; ss < 16; ss++) {
                const float4* hr = (const float4*)(A_h + (w * 16 + ss) * 20);
                ull av = pk2(vals[ss] * inv, vals[ss] * inv);
#pragma unroll
                for (int i = 0; i < 4; i++) {
                    float4 hv = hr[i];
                    acc[2*i]   = ffma2(av, pk2(hv.x, hv.y), acc[2*i]);
                    acc[2*i+1] = ffma2(av, pk2(hv.z, hv.w), acc[2*i+1]);
                }
            }
            ull xp[8];
#pragma unroll
            for (int i = 0; i < 8; i++) {
                float2 v = upk2(acc[i]);
                float a = (v.x > 0.f) ? v.x : (__expf(v.x) - 1.f);
                float b = (v.y > 0.f) ? v.y : (__expf(v.y) - 1.f);
                xp[i] = pk2(a, b);
            }
            float y[16];
#pragma unroll
            for (int d = 0; d < 16; d++)
                y[d] = __ldg(te_b + d) + __ldg(pe + w * 16 + d) +
                       dot16g(xp, (const float4*)(te_W + d * 16));
#pragma unroll
            for (int i = 0; i < 4; i++)
                *(float4*)(A_xe + tid*20 + i*4) = make_float4(y[4*i], y[4*i+1], y[4*i+2], y[4*i+3]);
        }
    } else {
        // ======== concurrent weight staging (warps 2-15, 448 threads) ========
        const int tid2 = tid - 64;
        {   // float4 bulk copies (contiguous, no remap)
            const float4* s1 = (const float4*)qkv_W;  float4* d1 = (float4*)s_qkvW;
            for (int i = tid2; i < 384; i += 448) d1[i] = __ldg(s1 + i);
            const float4* s2 = (const float4*)out_W;  float4* d2 = (float4*)s_outW;
            for (int i = tid2; i < 128; i += 448) d2[i] = __ldg(s2 + i);
            const float4* s3 = (const float4*)ff1_W;  float4* d3 = (float4*)s_ff1W;
            for (int i = tid2; i < 512; i += 448) d3[i] = __ldg(s3 + i);
            const float4* s4 = (const float4*)ff2_W;  float4* d4 = (float4*)s_ff2W;
            for (int i = tid2; i < 512; i += 448) d4[i] = __ldg(s4 + i);
        }
        if (tid2 < 96)  s_qkvb[tid2] = __ldg(qkv_b + tid2);
        if (tid2 >= 96 && tid2 < 128)  s_outb[tid2-96]  = __ldg(out_b + tid2-96);
        if (tid2 >= 128 && tid2 < 160) s_ln1g[tid2-128] = __ldg(ln1_g + tid2-128);
        if (tid2 >= 160 && tid2 < 192) s_ln1b[tid2-160] = __ldg(ln1_b + tid2-160);
        if (tid2 >= 192 && tid2 < 320) s_ff1b[tid2-192] = __ldg(ff1_b + tid2-192);
        if (tid2 >= 320 && tid2 < 352) s_ff2b[tid2-320] = __ldg(ff2_b + tid2-320);
        if (tid2 >= 352 && tid2 < 384) s_ln2g[tid2-352] = __ldg(ln2_g + tid2-352);
        if (tid2 >= 384 && tid2 < 416) s_ln2b[tid2-384] = __ldg(ln2_b + tid2-384);
    }
    __syncthreads();

    const float inv_sqrt_hd = 0.35355339059327373f;

    for (int l = 0; l < 2; l++) {
        // ---- qkv (16 warps; 6 outputs per active lane) ----
        if (tok_ok) {
            ull xp[8]; loadx(A_xe + tk * 20, xp);
#pragma unroll
            for (int i6 = 0; i6 < 6; i6++) {
                int j = pp + i6 * 8;
                A_qkv[tk * 52 + j] = s_qkvb[l * 48 + j] +
                    dot16p(xp, (const float4*)(s_qkvW + l * 768 + j * 16));
            }
        }
        __syncthreads();

        // ---- attention + out-proj + residual + LN1 (2 threads/token, fused) ----
        if (tid < 96) {
            int tk2 = tid >> 1, h2 = tid & 1;
            int b = tk2 & 15;
            const float4* qr = (const float4*)(A_qkv + tk2 * 52 + h2 * 8);
            float4 q0 = qr[0], q1 = qr[1];
            float sc[3], mx = -1e30f;
#pragma unroll
            for (int ks = 0; ks < 3; ks++) {
                const float4* kr = (const float4*)(A_qkv + (ks * 16 + b) * 52 + 16 + h2 * 8);
                float4 k0 = kr[0], k1 = kr[1];
                float s = q0.x*k0.x + q0.y*k0.y + q0.z*k0.z + q0.w*k0.w
                        + q1.x*k1.x + q1.y*k1.y + q1.z*k1.z + q1.w*k1.w;
                s *= inv_sqrt_hd;
                sc[ks] = s; mx = fmaxf(mx, s);
            }
            float sum = 0.f;
#pragma unroll
            for (int ks = 0; ks < 3; ks++) { sc[ks] = __expf(sc[ks] - mx); sum += sc[ks]; }
            float inv = 1.f / sum;
            float ctx[8] = {0,0,0,0,0,0,0,0};
#pragma unroll
            for (int ks = 0; ks < 3; ks++) {
                const float4* vr = (const float4*)(A_qkv + (ks * 16 + b) * 52 + 32 + h2 * 8);
                float4 v0 = vr[0], v1 = vr[1];
                float w = sc[ks];
                ctx[0] += w*v0.x; ctx[1] += w*v0.y; ctx[2] += w*v0.z; ctx[3] += w*v0.w;
                ctx[4] += w*v1.x; ctx[5] += w*v1.y; ctx[6] += w*v1.z; ctx[7] += w*v1.w;
            }
#pragma unroll
            for (int e = 0; e < 8; e++) ctx[e] *= inv;
            float full[16];
#pragma unroll
            for (int e = 0; e < 8; e++) {
                float o = __shfl_xor_sync(0xffffffffu, ctx[e], 1);
                if (h2 == 0) { full[e] = ctx[e]; full[8+e] = o; }
                else         { full[e] = o;      full[8+e] = ctx[e]; }
            }
            ull xp[8];
#pragma unroll
            for (int i = 0; i < 8; i++) xp[i] = pk2(full[2*i], full[2*i+1]);
            float4 r0 = *(const float4*)(A_xe + tk2 * 20 + h2 * 8);
            float4 r1 = *(const float4*)(A_xe + tk2 * 20 + h2 * 8 + 4);
            float resid[8] = { r0.x, r0.y, r0.z, r0.w, r1.x, r1.y, r1.z, r1.w };
            float y[8];
#pragma unroll
            for (int k = 0; k < 8; k++) {
                int d = h2 * 8 + k;
                y[k] = s_outb[l * 16 + d] + resid[k] +
                       dot16p(xp, (const float4*)(s_outW + l * 256 + d * 16));
            }
            float ls = 0.f, lq = 0.f;
#pragma unroll
            for (int k = 0; k < 8; k++) { ls += y[k]; lq += y[k] * y[k]; }
            ls += __shfl_xor_sync(0xffffffffu, ls, 1);
            lq += __shfl_xor_sync(0xffffffffu, lq, 1);
            float m = ls * 0.0625f;
            float rin = rsqrtf(lq * 0.0625f - m * m + 1e-5f);
#pragma unroll
            for (int k = 0; k < 8; k++) {
                int d = h2 * 8 + k;
                y[k] = (y[k] - m) * rin * s_ln1g[l * 16 + d] + s_ln1b[l * 16 + d];
            }
            *(float4*)(A_xe + tk2 * 20 + h2 * 8)     = make_float4(y[0], y[1], y[2], y[3]);
            *(float4*)(A_xe + tk2 * 20 + h2 * 8 + 4) = make_float4(y[4], y[5], y[6], y[7]);
        }
        __syncthreads();

        // ---- ff1 (relu), 8 contiguous outputs per active lane ----
        if (tok_ok) {
            ull xp[8]; loadx(A_xe + tk * 20, xp);
            float y[8];
#pragma unroll
            for (int k = 0; k < 8; k++) {
                int f = pp * 8 + k;
                y[k] = fmaxf(s_ff1b[l * 64 + f] +
                             dot16p(xp, (const float4*)(s_ff1W + l * 1024 + f * 16)), 0.f);
            }
            *(float4*)(A_hid + tk * 68 + pp * 8)     = make_float4(y[0], y[1], y[2], y[3]);
            *(float4*)(A_hid + tk * 68 + pp * 8 + 4) = make_float4(y[4], y[5], y[6], y[7]);
        }
        __syncthreads();

        // ---- ff2 + residual + LN2 (4 threads/token) ----
        if (tid < 192) {
            int tk2 = tid >> 2, q = tid & 3;
            const float4* hr = (const float4*)(A_hid + tk2 * 68);
            const float4* w40 = (const float4*)(s_ff2W + l * 1024 + (q * 4 + 0) * 64);
            const float4* w41 = (const float4*)(s_ff2W + l * 1024 + (q * 4 + 1) * 64);
            const float4* w42 = (const float4*)(s_ff2W + l * 1024 + (q * 4 + 2) * 64);
            const float4* w43 = (const float4*)(s_ff2W + l * 1024 + (q * 4 + 3) * 64);
            ull a0[4] = {0,0,0,0}, a1[4] = {0,0,0,0};
#pragma unroll
            for (int i = 0; i < 16; i++) {
                float4 h4 = hr[i];
                ull h0 = pk2(h4.x, h4.y), h1 = pk2(h4.z, h4.w);
                float4 w0 = w40[i], w1 = w41[i], w2 = w42[i], w3 = w43[i];
                a0[0] = ffma2(h0, pk2(w0.x, w0.y), a0[0]); a1[0] = ffma2(h1, pk2(w0.z, w0.w), a1[0]);
                a0[1] = ffma2(h0, pk2(w1.x, w1.y), a0[1]); a1[1] = ffma2(h1, pk2(w1.z, w1.w), a1[1]);
                a0[2] = ffma2(h0, pk2(w2.x, w2.y), a0[2]); a1[2] = ffma2(h1, pk2(w2.z, w2.w), a1[2]);
                a0[3] = ffma2(h0, pk2(w3.x, w3.y), a0[3]); a1[3] = ffma2(h1, pk2(w3.z, w3.w), a1[3]);
            }
            float y[4], ls = 0.f, lq = 0.f;
#pragma unroll
            for (int k = 0; k < 4; k++) {
                int d = q * 4 + k;
                float2 s0 = upk2(a0[k]), s1 = upk2(a1[k]);
                y[k] = (s0.x + s1.x) + (s0.y + s1.y) + s_ff2b[l * 16 + d] + A_xe[tk2 * 20 + d];
                ls += y[k]; lq += y[k] * y[k];
            }
            ls += __shfl_xor_sync(0xffffffffu, ls, 1);
            lq += __shfl_xor_sync(0xffffffffu, lq, 1);
            ls += __shfl_xor_sync(0xffffffffu, ls, 2);
            lq += __shfl_xor_sync(0xffffffffu, lq, 2);
            float m = ls * 0.0625f;
            float rin = rsqrtf(lq * 0.0625f - m * m + 1e-5f);
#pragma unroll
            for (int k = 0; k < 4; k++) {
                int d = q * 4 + k;
                y[k] = (y[k] - m) * rin * s_ln2g[l * 16 + d] + s_ln2b[l * 16 + d];
            }
            *(float4*)(A_xe + tk2 * 20 + q * 4) = make_float4(y[0], y[1], y[2], y[3]);
        }
        __syncthreads();
    }

    // ---- decoder: warp = output row, latent read from smem ----
    {
        ull a0 = 0ull, a1 = 0ull;
#pragma unroll
        for (int i = 0; i < 6; i++) {
            int j = i * 128 + 4 * lane;        // latent index (host-major)
            int n = j / 48, rem = j - n * 48;
            int ww = rem >> 4, d = rem & 15;
            float4 x = *(const float4*)(A_xe + (ww * 16 + n) * 20 + d);
            a0 = ffma2(pk2(x.x, x.y), pk2(wreg[i].x, wreg[i].y), a0);
            a1 = ffma2(pk2(x.z, x.w), pk2(wreg[i].z, wreg[i].w), a1);
        }
        float2 s0 = upk2(a0), s1 = upk2(a1);
        float s = (s0.x + s1.x) + (s0.y + s1.y);
#pragma unroll
        for (int o = 16; o; o >>= 1) s += __shfl_xor_sync(0xffffffffu, s, o);
        if (lane == 0) {
            s += bias_reg;
            if (row >= 32) s = 1.f / (1.f + __expf(-s));
            out[row] = s;
        }
    }
}

extern "C" void kernel_launch(void* const* d_in, const int* in_sizes, int n_in,
                              void* d_out, int out_size) {
    const int smem_bytes = 14336 * 4;
    cudaFuncSetAttribute(fused_kernel, cudaFuncAttributeMaxDynamicSharedMemorySize, smem_bytes);
    fused_kernel<<<10, NT, smem_bytes>>>(
        (const float*)d_in[0],
        (const float*)d_in[2], (const float*)d_in[3], (const float*)d_in[4],
        (const float*)d_in[5], (const float*)d_in[6], (const float*)d_in[7],
        (const float*)d_in[8], (const float*)d_in[9],
        (const float*)d_in[10], (const float*)d_in[11],
        (const float*)d_in[12], (const float*)d_in[13],
        (const float*)d_in[14], (const float*)d_in[15],
        (const float*)d_in[16], (const float*)d_in[17],
        (const float*)d_in[18], (const float*)d_in[19],
        (const float*)d_in[20], (const float*)d_in[21],
        (const float*)d_in[22], (const float*)d_in[23],
        (float*)d_out);
}

// round 10
// speedup vs baseline: 1.5724x; 1.2959x over previous
#include <cuda_runtime.h>
#include <math.h>

#define NT 512
typedef unsigned long long ull;

// ---- packed f32x2 helpers (sm_103a) ----
__device__ __forceinline__ ull pk2(float lo, float hi) {
    ull r; asm("mov.b64 %0, {%1,%2};" : "=l"(r) : "f"(lo), "f"(hi)); return r;
}
__device__ __forceinline__ float2 upk2(ull v) {
    float2 r; asm("mov.b64 {%0,%1}, %2;" : "=f"(r.x), "=f"(r.y) : "l"(v)); return r;
}
__device__ __forceinline__ ull ffma2(ull a, ull b, ull c) {
    ull d; asm("fma.rn.f32x2 %0, %1, %2, %3;" : "=l"(d) : "l"(a), "l"(b), "l"(c)); return d;
}
__device__ __forceinline__ void loadx(const float* p, ull* xp) {
    const float4* p4 = (const float4*)p;
#pragma unroll
    for (int i = 0; i < 4; i++) {
        float4 v = p4[i];
        xp[2*i]   = pk2(v.x, v.y);
        xp[2*i+1] = pk2(v.z, v.w);
    }
}
// dot16: packed x, SMEM float4 weight row (warp-uniform -> broadcast)
__device__ __forceinline__ float dot16p(const ull* xp, const float4* w4) {
    ull a0 = 0ull, a1 = 0ull;
#pragma unroll
    for (int i = 0; i < 4; i++) {
        float4 w = w4[i];
        a0 = ffma2(xp[2*i],   pk2(w.x, w.y), a0);
        a1 = ffma2(xp[2*i+1], pk2(w.z, w.w), a1);
    }
    float2 s0 = upk2(a0), s1 = upk2(a1);
    return (s0.x + s1.x) + (s0.y + s1.y);
}
// dot16: packed x, GLOBAL float4 weight row (overlapped prologue only)
__device__ __forceinline__ float dot16g(const ull* xp, const float4* __restrict__ w4) {
    float4 w0 = __ldg(w4), w1 = __ldg(w4+1), w2 = __ldg(w4+2), w3 = __ldg(w4+3);
    ull a0 = 0ull, a1 = 0ull;
    a0 = ffma2(xp[0], pk2(w0.x, w0.y), a0); a1 = ffma2(xp[1], pk2(w0.z, w0.w), a1);
    a0 = ffma2(xp[2], pk2(w1.x, w1.y), a0); a1 = ffma2(xp[3], pk2(w1.z, w1.w), a1);
    a0 = ffma2(xp[4], pk2(w2.x, w2.y), a0); a1 = ffma2(xp[5], pk2(w2.z, w2.w), a1);
    a0 = ffma2(xp[6], pk2(w3.x, w3.y), a0); a1 = ffma2(xp[7], pk2(w3.z, w3.w), a1);
    float2 s0 = upk2(a0), s1 = upk2(a1);
    return (s0.x + s1.x) + (s0.y + s1.y);
}

__global__ __launch_bounds__(NT, 1) void fused_kernel(
    const float* __restrict__ t,
    const float* __restrict__ gat_W, const float* __restrict__ a_src, const float* __restrict__ a_dst,
    const float* __restrict__ te_W, const float* __restrict__ te_b, const float* __restrict__ pe,
    const float* __restrict__ qkv_W, const float* __restrict__ qkv_b,
    const float* __restrict__ out_W, const float* __restrict__ out_b,
    const float* __restrict__ ln1_g, const float* __restrict__ ln1_b,
    const float* __restrict__ ff1_W, const float* __restrict__ ff1_b,
    const float* __restrict__ ff2_W, const float* __restrict__ ff2_b,
    const float* __restrict__ ln2_g, const float* __restrict__ ln2_b,
    const float* __restrict__ an_W, const float* __restrict__ an_b,
    const float* __restrict__ pr_W, const float* __restrict__ pr_b,
    float* __restrict__ out)
{
    const int tid  = threadIdx.x;
    const int warp = tid >> 5;
    const int lane = tid & 31;
    const int g    = warp & 1;
    const int tk   = g * 32 + lane;
    const int pp   = warp >> 1;
    const bool tok_ok = tk < 48;

    // ---- decoder weight prefetch (registers; hidden behind encoder) ----
    const int row = blockIdx.x * 16 + warp;   // 0..159
    const float4* wp = (row < 32) ? (const float4*)(an_W + row * 768)
                                  : (const float4*)(pr_W + (row - 32) * 768);
    float bias_reg = (row < 32) ? an_b[row] : pr_b[row - 32];
    float4 wreg[6];
#pragma unroll
    for (int i = 0; i < 6; i++) wreg[i] = __ldg(wp + i * 32 + lane);

    extern __shared__ float sm[];
    float* s_qkvW = sm;            // 1536 (contiguous; uniform reads)
    float* s_qkvb = sm + 1536;     // 96
    float* s_outW = sm + 1632;     // 512 (contiguous; row-parallel reads)
    float* s_outb = sm + 2144;     // 32
    float* s_ln1g = sm + 2176;     // 32
    float* s_ln1b = sm + 2208;     // 32
    float* s_ff1W = sm + 2240;     // 2048 (contiguous; uniform reads)
    float* s_ff1b = sm + 4288;     // 128
    float* s_ff2W = sm + 4416;     // 2176 (stride 68: conflict-free for q-spread)
    float* s_ff2b = sm + 6592;     // 32
    float* s_ln2g = sm + 6624;     // 32
    float* s_ln2b = sm + 6656;     // 32
    float* A_h    = sm + 6688;     // 48*20
    float* A_xe   = sm + 7648;     // 48*20
    float* A_qkv  = sm + 8608;     // 48*52
    float* A_hid  = sm + 11104;    // 48*68
    float* A_e    = sm + 14368;    // 96

    if (warp < 2) {
        // ======== overlapped prologue: GAT P1 + P2 (weights from L2) ========
        if (tid < 48) {
            float x0 = __ldg(t + tid*3), x1 = __ldg(t + tid*3 + 1), x2 = __ldg(t + tid*3 + 2);
            float hrow[16];
            float es = 0.f, ed = 0.f;
#pragma unroll
            for (int f = 0; f < 16; f++) {
                float hv = x0*__ldg(gat_W+f) + x1*__ldg(gat_W+16+f) + x2*__ldg(gat_W+32+f);
                hrow[f] = hv;
                es += hv * __ldg(a_src+f);
                ed += hv * __ldg(a_dst+f);
            }
#pragma unroll
            for (int i = 0; i < 4; i++)
                *(float4*)(A_h + tid*20 + i*4) = make_float4(hrow[4*i], hrow[4*i+1], hrow[4*i+2], hrow[4*i+3]);
            A_e[tid] = es;
            A_e[48 + tid] = ed;
        }
        __syncwarp();   // window's tokens live in one warp -> intra-warp dep
        if (tid < 48) {
            int w = tid >> 4;
            float ed = A_e[48 + tid];
            float vals[16], mx = -1e30f;
#pragma unroll
            for (int s = 0; s < 16; s++) {
                float e = A_e[w * 16 + s] + ed;
                e = (e > 0.f) ? e : 0.2f * e;
                vals[s] = e; mx = fmaxf(mx, e);
            }
            float sum = 0.f;
#pragma unroll
            for (int s = 0; s < 16; s++) { vals[s] = __expf(vals[s] - mx); sum += vals[s]; }
            float inv = 1.f / sum;
            ull acc[8] = {0,0,0,0,0,0,0,0};
#pragma unroll
            for (int ss = 0; ss < 16; ss++) {
                const float4* hr = (const float4*)(A_h + (w * 16 + ss) * 20);
                ull av = pk2(vals[ss] * inv, vals[ss] * inv);
#pragma unroll
                for (int i = 0; i < 4; i++) {
                    float4 hv = hr[i];
                    acc[2*i]   = ffma2(av, pk2(hv.x, hv.y), acc[2*i]);
                    acc[2*i+1] = ffma2(av, pk2(hv.z, hv.w), acc[2*i+1]);
                }
            }
            ull xp[8];
#pragma unroll
            for (int i = 0; i < 8; i++) {
                float2 v = upk2(acc[i]);
                float a = (v.x > 0.f) ? v.x : (__expf(v.x) - 1.f);
                float b = (v.y > 0.f) ? v.y : (__expf(v.y) - 1.f);
                xp[i] = pk2(a, b);
            }
            float y[16];
#pragma unroll
            for (int d = 0; d < 16; d++)
                y[d] = __ldg(te_b + d) + __ldg(pe + w * 16 + d) +
                       dot16g(xp, (const float4*)(te_W + d * 16));
#pragma unroll
            for (int i = 0; i < 4; i++)
                *(float4*)(A_xe + tid*20 + i*4) = make_float4(y[4*i], y[4*i+1], y[4*i+2], y[4*i+3]);
        }
    } else {
        // ======== concurrent weight staging (warps 2-15) ========
        const int tid2 = tid - 64;
        const float4* s1 = (const float4*)qkv_W;  float4* d1 = (float4*)s_qkvW;
        for (int i = tid2; i < 384; i += 448) d1[i] = __ldg(s1 + i);
        const float4* s2 = (const float4*)out_W;  float4* d2 = (float4*)s_outW;
        for (int i = tid2; i < 128; i += 448) d2[i] = __ldg(s2 + i);
        const float4* s3 = (const float4*)ff1_W;  float4* d3 = (float4*)s_ff1W;
        for (int i = tid2; i < 512; i += 448) d3[i] = __ldg(s3 + i);
        for (int i = tid2; i < 2048; i += 448)   // ff2: remap to stride 68
            s_ff2W[(i >> 6) * 68 + (i & 63)] = __ldg(ff2_W + i);
        if (tid2 < 96)  s_qkvb[tid2] = __ldg(qkv_b + tid2);
        if (tid2 >= 96 && tid2 < 128)  s_outb[tid2-96]  = __ldg(out_b + tid2-96);
        if (tid2 >= 128 && tid2 < 160) s_ln1g[tid2-128] = __ldg(ln1_g + tid2-128);
        if (tid2 >= 160 && tid2 < 192) s_ln1b[tid2-160] = __ldg(ln1_b + tid2-160);
        if (tid2 >= 192 && tid2 < 320) s_ff1b[tid2-192] = __ldg(ff1_b + tid2-192);
        if (tid2 >= 320 && tid2 < 352) s_ff2b[tid2-320] = __ldg(ff2_b + tid2-320);
        if (tid2 >= 352 && tid2 < 384) s_ln2g[tid2-352] = __ldg(ln2_g + tid2-352);
        if (tid2 >= 384 && tid2 < 416) s_ln2b[tid2-384] = __ldg(ln2_b + tid2-384);
    }
    __syncthreads();

    const float inv_sqrt_hd = 0.35355339059327373f;

    for (int l = 0; l < 2; l++) {
        // ---- qkv (16 warps; 6 outputs per active lane; uniform weight rows) ----
        if (tok_ok) {
            ull xp[8]; loadx(A_xe + tk * 20, xp);
#pragma unroll
            for (int i6 = 0; i6 < 6; i6++) {
                int j = pp + i6 * 8;
                A_qkv[tk * 52 + j] = s_qkvb[l * 48 + j] +
                    dot16p(xp, (const float4*)(s_qkvW + l * 768 + j * 16));
            }
        }
        __syncthreads();

        // ---- attention + out-proj + residual + LN1 (192 threads = 4/token) ----
        if (tid < 192) {
            const int tk2 = tid >> 2;          // token
            const int q4  = tid & 3;           // quarter: h2 = q4>>1, half = q4&1
            const int h2  = q4 >> 1;
            const int hf  = q4 & 1;
            const int b   = tk2 & 15;
            // q (4 dims of own head/half)
            float4 qv = *(const float4*)(A_qkv + tk2 * 52 + h2 * 8 + hf * 4);
            float sc[3], mx = -1e30f;
#pragma unroll
            for (int ks = 0; ks < 3; ks++) {
                float4 kv = *(const float4*)(A_qkv + (ks * 16 + b) * 52 + 16 + h2 * 8 + hf * 4);
                float p = qv.x*kv.x + qv.y*kv.y + qv.z*kv.z + qv.w*kv.w;
                p += __shfl_xor_sync(0xffffffffu, p, 1);   // sum both halves
                p *= inv_sqrt_hd;
                sc[ks] = p; mx = fmaxf(mx, p);
            }
            float sum = 0.f;
#pragma unroll
            for (int ks = 0; ks < 3; ks++) { sc[ks] = __expf(sc[ks] - mx); sum += sc[ks]; }
            float inv = 1.f / sum;
            // ctx: own 4 dims (input dim offset = q4*4 of the 16-dim ctx)
            float c0 = 0.f, c1 = 0.f, c2 = 0.f, c3 = 0.f;
#pragma unroll
            for (int ks = 0; ks < 3; ks++) {
                float4 vv = *(const float4*)(A_qkv + (ks * 16 + b) * 52 + 32 + h2 * 8 + hf * 4);
                float w = sc[ks];
                c0 += w * vv.x; c1 += w * vv.y; c2 += w * vv.z; c3 += w * vv.w;
            }
            c0 *= inv; c1 *= inv; c2 *= inv; c3 *= inv;
            // out-proj partials over own 4 input dims, for all 16 outputs
            float part[16];
#pragma unroll
            for (int d = 0; d < 16; d++) {
                float4 w = *(const float4*)(s_outW + l * 256 + d * 16 + q4 * 4);
                part[d] = c0*w.x + c1*w.y + c2*w.z + c3*w.w;
            }
            // tree-reduce across 4 threads; thread q4 ends owning d in [q4*4, q4*4+4)
            const int bm = (q4 < 2) ? 0 : 8;       // my 8-output base after step1
            const int bo = 8 - bm;
            float s1v[8];
#pragma unroll
            for (int i = 0; i < 8; i++)
                s1v[i] = part[bm + i] + __shfl_xor_sync(0xffffffffu, part[bo + i], 2);
            const int mr = (q4 & 1) * 4;           // my 4-output offset within s1v
            const int orr = 4 - mr;
            float y[4];
#pragma unroll
            for (int k = 0; k < 4; k++)
                y[k] = s1v[mr + k] + __shfl_xor_sync(0xffffffffu, s1v[orr + k], 1);
            // residual + bias
            float4 resid = *(const float4*)(A_xe + tk2 * 20 + q4 * 4);
            y[0] += resid.x + s_outb[l*16 + q4*4 + 0];
            y[1] += resid.y + s_outb[l*16 + q4*4 + 1];
            y[2] += resid.z + s_outb[l*16 + q4*4 + 2];
            y[3] += resid.w + s_outb[l*16 + q4*4 + 3];
            // LN over 4 threads
            float ls = y[0]+y[1]+y[2]+y[3];
            float lq = y[0]*y[0]+y[1]*y[1]+y[2]*y[2]+y[3]*y[3];
            ls += __shfl_xor_sync(0xffffffffu, ls, 1);
            lq += __shfl_xor_sync(0xffffffffu, lq, 1);
            ls += __shfl_xor_sync(0xffffffffu, ls, 2);
            lq += __shfl_xor_sync(0xffffffffu, lq, 2);
            float m = ls * 0.0625f;
            float rin = rsqrtf(lq * 0.0625f - m * m + 1e-5f);
#pragma unroll
            for (int k = 0; k < 4; k++) {
                int d = q4 * 4 + k;
                y[k] = (y[k] - m) * rin * s_ln1g[l * 16 + d] + s_ln1b[l * 16 + d];
            }
            *(float4*)(A_xe + tk2 * 20 + q4 * 4) = make_float4(y[0], y[1], y[2], y[3]);
        }
        __syncthreads();

        // ---- ff1 (relu), 8 contiguous outputs per active lane; uniform rows ----
        if (tok_ok) {
            ull xp[8]; loadx(A_xe + tk * 20, xp);
            float y[8];
#pragma unroll
            for (int k = 0; k < 8; k++) {
                int f = pp * 8 + k;
                y[k] = fmaxf(s_ff1b[l * 64 + f] +
                             dot16p(xp, (const float4*)(s_ff1W + l * 1024 + f * 16)), 0.f);
            }
            *(float4*)(A_hid + tk * 68 + pp * 8)     = make_float4(y[0], y[1], y[2], y[3]);
            *(float4*)(A_hid + tk * 68 + pp * 8 + 4) = make_float4(y[4], y[5], y[6], y[7]);
        }
        __syncthreads();

        // ---- ff2 + residual + LN2 (192 threads = 4/token; d = q4 + 4k, bank-free) ----
        if (tid < 192) {
            const int tk2 = tid >> 2, q4 = tid & 3;
            const float4* hr = (const float4*)(A_hid + tk2 * 68);
            // 4 interleaved output rows: (q4 + 4k), rows 68 apart -> banks 0/4/8/12
            const float4* wr0 = (const float4*)(s_ff2W + l * 1088 + (q4 + 0)  * 68);
            const float4* wr1 = (const float4*)(s_ff2W + l * 1088 + (q4 + 4)  * 68);
            const float4* wr2 = (const float4*)(s_ff2W + l * 1088 + (q4 + 8)  * 68);
            const float4* wr3 = (const float4*)(s_ff2W + l * 1088 + (q4 + 12) * 68);
            ull a0[4] = {0,0,0,0}, a1[4] = {0,0,0,0};
#pragma unroll
            for (int i = 0; i < 16; i++) {
                float4 h4 = hr[i];
                ull h0 = pk2(h4.x, h4.y), h1 = pk2(h4.z, h4.w);
                float4 w0 = wr0[i], w1 = wr1[i], w2 = wr2[i], w3 = wr3[i];
                a0[0] = ffma2(h0, pk2(w0.x, w0.y), a0[0]); a1[0] = ffma2(h1, pk2(w0.z, w0.w), a1[0]);
                a0[1] = ffma2(h0, pk2(w1.x, w1.y), a0[1]); a1[1] = ffma2(h1, pk2(w1.z, w1.w), a1[1]);
                a0[2] = ffma2(h0, pk2(w2.x, w2.y), a0[2]); a1[2] = ffma2(h1, pk2(w2.z, w2.w), a1[2]);
                a0[3] = ffma2(h0, pk2(w3.x, w3.y), a0[3]); a1[3] = ffma2(h1, pk2(w3.z, w3.w), a1[3]);
            }
            float y[4], ls = 0.f, lq = 0.f;
#pragma unroll
            for (int k = 0; k < 4; k++) {
                int d = q4 + 4 * k;
                float2 s0 = upk2(a0[k]), s1 = upk2(a1[k]);
                y[k] = (s0.x + s1.x) + (s0.y + s1.y) + s_ff2b[l * 16 + d] + A_xe[tk2 * 20 + d];
                ls += y[k]; lq += y[k] * y[k];
            }
            ls += __shfl_xor_sync(0xffffffffu, ls, 1);
            lq += __shfl_xor_sync(0xffffffffu, lq, 1);
            ls += __shfl_xor_sync(0xffffffffu, ls, 2);
            lq += __shfl_xor_sync(0xffffffffu, lq, 2);
            float m = ls * 0.0625f;
            float rin = rsqrtf(lq * 0.0625f - m * m + 1e-5f);
#pragma unroll
            for (int k = 0; k < 4; k++) {
                int d = q4 + 4 * k;
                A_xe[tk2 * 20 + d] = (y[k] - m) * rin * s_ln2g[l * 16 + d] + s_ln2b[l * 16 + d];
            }
        }
        __syncthreads();
    }

    // ---- decoder: warp = output row, latent read from smem ----
    {
        ull a0 = 0ull, a1 = 0ull;
#pragma unroll
        for (int i = 0; i < 6; i++) {
            int j = i * 128 + 4 * lane;        // latent index (host-major)
            int n = j / 48, rem = j - n * 48;
            int ww = rem >> 4, d = rem & 15;
            float4 x = *(const float4*)(A_xe + (ww * 16 + n) * 20 + d);
            a0 = ffma2(pk2(x.x, x.y), pk2(wreg[i].x, wreg[i].y), a0);
            a1 = ffma2(pk2(x.z, x.w), pk2(wreg[i].z, wreg[i].w), a1);
        }
        float2 s0 = upk2(a0), s1 = upk2(a1);
        float s = (s0.x + s1.x) + (s0.y + s1.y);
#pragma unroll
        for (int o = 16; o; o >>= 1) s += __shfl_xor_sync(0xffffffffu, s, o);
        if (lane == 0) {
            s += bias_reg;
            if (row >= 32) s = 1.f / (1.f + __expf(-s));
            out[row] = s;
        }
    }
}

extern "C" void kernel_launch(void* const* d_in, const int* in_sizes, int n_in,
                              void* d_out, int out_size) {
    const int smem_bytes = 14464 * 4;
    cudaFuncSetAttribute(fused_kernel, cudaFuncAttributeMaxDynamicSharedMemorySize, smem_bytes);
    fused_kernel<<<10, NT, smem_bytes>>>(
        (const float*)d_in[0],
        (const float*)d_in[2], (const float*)d_in[3], (const float*)d_in[4],
        (const float*)d_in[5], (const float*)d_in[6], (const float*)d_in[7],
        (const float*)d_in[8], (const float*)d_in[9],
        (const float*)d_in[10], (const float*)d_in[11],
        (const float*)d_in[12], (const float*)d_in[13],
        (const float*)d_in[14], (const float*)d_in[15],
        (const float*)d_in[16], (const float*)d_in[17],
        (const float*)d_in[18], (const float*)d_in[19],
        (const float*)d_in[20], (const float*)d_in[21],
        (const float*)d_in[22], (const float*)d_in[23],
        (float*)d_out);
}